// round 10
// baseline (speedup 1.0000x reference)
#include <cuda_runtime.h>

// Guided filter, fully fused, SMEM-free warp-sliding.
// R9 math (4-shuffle HQ, x9 algebra, guard peel) restructured:
//  - 2-deep sliding-sum state (P = h[rr]+h[rr+1], hprev = h[rr+1]) instead of
//    3-deep rings -> uniform step, no slot rotation, fewer live regs.
//  - one-row register prefetch (pointer bumps only, no index math).
//  - unroll-by-4 rolled loop (fits L0 I$) + 4 peeled guarded steps.

#define W 1024
#define H 1024
#define EPS81 8.1e-5f           // 81 * 1e-6
#define C9 (1.0f / 9.0f)

#define OUT_COLS_PER_WARP 28
#define BANDS 37                // ceil(1024 / 28)
#define CHUNK_H 128
#define CHUNKS (H / CHUNK_H)    // 8
#define WARPS_PER_BLOCK 8
#define UNITS (24 * BANDS * CHUNKS)                 // 7104 warps
#define NBLOCKS (UNITS / WARPS_PER_BLOCK)           // 888

__global__ __launch_bounds__(256, 6) void gf_kernel(const float* __restrict__ x,
                                                    const float* __restrict__ y,
                                                    float* __restrict__ out)
{
    const int wid  = threadIdx.x >> 5;
    const int lane = threadIdx.x & 31;
    const int g    = blockIdx.x * WARPS_PER_BLOCK + wid;

    const int plane = g / (BANDS * CHUNKS);
    const int rem   = g - plane * (BANDS * CHUNKS);
    const int band  = rem / CHUNKS;
    const int chunk = rem - band * CHUNKS;

    const int cbase = band * OUT_COLS_PER_WARP - 2;
    const int icr   = cbase + lane;                  // raw column of this lane
    const int ic    = min(max(icr, 0), W - 1);       // clamped load column
    const int r0    = chunk * CHUNK_H;

    const bool pl = (icr == 0);          // stage-2 left replication
    const bool pr = (icr == W - 1);      // stage-2 right replication
    const bool do_store = (lane >= 2) && (lane <= 29) && (icr >= 0) && (icr < W);

    const size_t pb = (size_t)plane * (W * H);
    const float* __restrict__ px = x + pb + ic;
    const float* __restrict__ py = y + pb + ic;
    float* po = out + pb + (size_t)r0 * W + ic;      // ic == icr wherever stored

    // Horizontal sums from 4 shuffles; hxy/hxx rebuilt from neighbors via FMA.
#define HQ(xv, yv, HX, HY, HXY, HXX) { \
    float xl = __shfl_up_sync(0xffffffffu, xv, 1); \
    float xr = __shfl_down_sync(0xffffffffu, xv, 1); \
    float yl = __shfl_up_sync(0xffffffffu, yv, 1); \
    float yr = __shfl_down_sync(0xffffffffu, yv, 1); \
    HX = xl + xv + xr; \
    HY = yl + yv + yr; \
    HXY = fmaf(xl, yl, fmaf(xr, yr, xv * yv)); \
    HXX = fmaf(xl, xl, fmaf(xr, xr, xv * xv)); }

    // A,b9: A = (9*Sxy - Sx*Sy)/(9*Sxx - Sx^2 + 81e), b9 = Sy - A*Sx, then
    // horizontal 3-sum of both with col-edge replication.
#define ABROW(Sx, Sy, Sxy, Sxx, HA, HB) { \
    float t   = (Sx) * (Sy); \
    float num = fmaf((Sxy), 9.0f, -t); \
    float u   = fmaf(-(Sx), (Sx), EPS81); \
    float den = fmaf((Sxx), 9.0f, u); \
    float Av  = __fdividef(num, den); \
    float Bv  = fmaf(-Av, (Sx), (Sy)); \
    float Al = __shfl_up_sync(0xffffffffu, Av, 1); \
    float Ar = __shfl_down_sync(0xffffffffu, Av, 1); \
    float Bl = __shfl_up_sync(0xffffffffu, Bv, 1); \
    float Br = __shfl_down_sync(0xffffffffu, Bv, 1); \
    Al = pl ? Av : Al;  Bl = pl ? Bv : Bl; \
    Ar = pr ? Av : Ar;  Br = pr ? Bv : Br; \
    HA = Al + Av + Ar; \
    HB = Bl + Bv + Br; }

    // Sliding-sum state. Invariant at the top of the step for output row rr:
    //   hp*  = h at input row rr+1        P*  = h[rr] + h[rr+1]
    //   hAp  = hA at A-row rr             PA  = hA[rr-1] + hA[rr]   (same for B)
    //   xc0 = x[rr], xc1 = x[rr+1]
    //   (nxv,nyv) = input row min(rr+2, H-1); pxr/pyr -> row min(rr+3, H-1)
    float hpx, hpy, hpxy, hpxx, Px, Py, Pxy, Pxx;
    float hAp, hBp, PA, PB;
    float xc0, xc1;
    float nxv, nyv;

    // ---------------- prologue ----------------
    {
        float t0x, t0y, t0xy, t0xx, t1x, t1y, t1xy, t1xx;
        float h0x, h0y, h0xy, h0xx, h1x, h1y, h1xy, h1xx;
        { int rc = max(r0 - 2, 0);
          float xv = px[(size_t)rc * W], yv = py[(size_t)rc * W];
          HQ(xv, yv, t0x, t0y, t0xy, t0xx) }
        { int rc = max(r0 - 1, 0);
          float xv = px[(size_t)rc * W], yv = py[(size_t)rc * W];
          HQ(xv, yv, t1x, t1y, t1xy, t1xx) }
        { float xv = px[(size_t)r0 * W], yv = py[(size_t)r0 * W];
          HQ(xv, yv, h0x, h0y, h0xy, h0xx) xc0 = xv; }
        { float xv = px[(size_t)(r0 + 1) * W], yv = py[(size_t)(r0 + 1) * W];
          HQ(xv, yv, h1x, h1y, h1xy, h1xx) xc1 = xv; }

        float hAm, hBm, hA0, hB0;
        ABROW(t0x + t1x + h0x, t0y + t1y + h0y,
              t0xy + t1xy + h0xy, t0xx + t1xx + h0xx, hAm, hBm)   // A row r0-1
        ABROW(t1x + h0x + h1x, t1y + h0y + h1y,
              t1xy + h0xy + h1xy, t1xx + h0xx + h1xx, hA0, hB0)   // A row r0
        if (r0 == 0) { hAm = hA0; hBm = hB0; }   // top: A(-1) := A(0)

        hpx = h1x;  hpy = h1y;  hpxy = h1xy;  hpxx = h1xx;
        Px = h0x + h1x;  Py = h0y + h1y;
        Pxy = h0xy + h1xy;  Pxx = h0xx + h1xx;
        hAp = hA0;  hBp = hB0;
        PA = hAm + hA0;  PB = hBm + hB0;
    }

    const float* pxr = px + (size_t)(r0 + 3) * W;   // r0+3 <= 899, always valid
    const float* pyr = py + (size_t)(r0 + 3) * W;
    nxv = px[(size_t)(r0 + 2) * W];
    nyv = py[(size_t)(r0 + 2) * W];

    // Core of one step (input row rr+2 already in xv/yv).
#define SCORE(xv, yv) \
    float nx_, ny_, nxy_, nxx_; \
    HQ(xv, yv, nx_, ny_, nxy_, nxx_) \
    float Sx = Px + nx_, Sy = Py + ny_; \
    float Sxy = Pxy + nxy_, Sxx = Pxx + nxx_; \
    Px = hpx + nx_;  Py = hpy + ny_; \
    Pxy = hpxy + nxy_;  Pxx = hpxx + nxx_; \
    hpx = nx_;  hpy = ny_;  hpxy = nxy_;  hpxx = nxx_; \
    float hAn, hBn; \
    ABROW(Sx, Sy, Sxy, Sxx, hAn, hBn)

#define STAIL(xv) \
    float SA = PA + hAn, SB = PB + hBn; \
    PA = hAp + hAn;  PB = hBp + hBn; \
    hAp = hAn;  hBp = hBn; \
    float res = fmaf(SA, xc0, SB * C9) * C9; \
    res = fminf(fmaxf(truncf(res), 0.0f), 255.0f); \
    if (do_store) *po = res; \
    po += W; \
    xc0 = xc1;  xc1 = xv;

    // Guard-free steps: valid while rr+3 <= H-1, i.e. i <= 124 for the last
    // chunk (r0=896 -> rr+3 = 1023 at i=124). We run i = 0..123.
#pragma unroll 4
    for (int i = 0; i < CHUNK_H - 4; ++i) {
        float xv = nxv, yv = nyv;
        nxv = *pxr;  nyv = *pyr;
        pxr += W;  pyr += W;
        SCORE(xv, yv)
        STAIL(xv)
    }

    // Guarded steps i = 124..127 (bottom-of-image replication; for non-last
    // chunks the conditions always take the "normal" path).
#define STEP_G(i) { \
        const int rr = r0 + (i); \
        float xv = nxv, yv = nyv; \
        nxv = *pxr;  nyv = *pyr; \
        if (rr + 4 < H) { pxr += W;  pyr += W; } \
        SCORE(xv, yv) \
        if (rr + 1 >= H) { hAn = hAp;  hBn = hBp; }   /* A(H) := A(H-1) */ \
        STAIL(xv) }

    STEP_G(CHUNK_H - 4)
    STEP_G(CHUNK_H - 3)
    STEP_G(CHUNK_H - 2)
    STEP_G(CHUNK_H - 1)
#undef STEP_G
#undef STAIL
#undef SCORE
#undef ABROW
#undef HQ
}

extern "C" void kernel_launch(void* const* d_in, const int* in_sizes, int n_in,
                              void* d_out, int out_size) {
    const float* x = (const float*)d_in[0];
    const float* y = (const float*)d_in[1];
    float* out     = (float*)d_out;

    gf_kernel<<<NBLOCKS, 32 * WARPS_PER_BLOCK>>>(x, y, out);
}

// round 11
// speedup vs baseline: 1.0252x; 1.0252x over previous
#include <cuda_runtime.h>

// Guided filter, fully fused, SMEM-free warp-sliding, 2 columns per lane.
// One warp covers 64 loaded columns (lane k -> cols cbase+2k, +1), outputs the
// middle 60 (lanes 1..30). MIO ops per step: 8 SHFL + 2 LDG.64 + 1 STG.64 for
// 60 outputs (vs 11 per 28 in the scalar version) -- attacks the measured MIO
// throughput wall. Sliding-sum state (2-deep), pointer-bump addressing,
// 128-thread blocks, 864 blocks = one co-resident wave.

#define W 1024
#define H 1024
#define EPS81 8.1e-5f           // 81 * 1e-6
#define C9 (1.0f / 9.0f)

#define OUTC 60
#define BANDS 18                // ceil(1024/60)
#define CHUNK_H 128
#define CHUNKS (H / CHUNK_H)    // 8
#define WPB 4                   // 128 threads
#define UNITS (24 * BANDS * CHUNKS)        // 3456 warps
#define NBLOCKS (UNITS / WPB)              // 864 blocks

__global__ __launch_bounds__(128, 8) void gf_kernel(const float* __restrict__ x,
                                                    const float* __restrict__ y,
                                                    float* __restrict__ out)
{
    const int wid  = threadIdx.x >> 5;
    const int lane = threadIdx.x & 31;
    const int g    = blockIdx.x * WPB + wid;

    const int plane = g / (BANDS * CHUNKS);
    const int rem   = g - plane * (BANDS * CHUNKS);
    const int band  = rem / CHUNKS;
    const int chunk = rem - band * CHUNKS;

    const int cfirst = band * OUTC - 2 + lane * 2;   // this lane's 2 columns
    const int cl     = min(max(cfirst, 0), W - 2);   // clamped aligned load col
    const int r0     = chunk * CHUNK_H;

    const bool dupL = (cfirst < 0);       // lane left of image: both elems = col 0
    const bool dupR = (cfirst >= W);      // lane right of image: both elems = col W-1
    const bool pl   = (cfirst == 0);      // elem .x is image col 0
    const bool pr   = (cfirst == W - 2);  // elem .y is image col 1023
    const bool do_store = (lane >= 1) && (lane <= 30) && (cfirst < W);

    const size_t pb = (size_t)plane * (size_t)(W * H);
    const float* __restrict__ px = x + pb + cl;
    const float* __restrict__ py = y + pb + cl;
    float* po = out + pb + (size_t)r0 * W + cfirst;

    // load + column-replication fixup
#define LD2(v, P, row) { \
    v = *reinterpret_cast<const float2*>((P) + (size_t)(row) * W); \
    if (dupL) v.y = v.x; \
    if (dupR) v.x = v.y; }
#define LDP(v, PTR) { \
    v = *reinterpret_cast<const float2*>(PTR); \
    if (dupL) v.y = v.x; \
    if (dupR) v.x = v.y; }

    // Horizontal 3-sums for a float2 pair: 4 shuffles total.
#define HQ2(xv, yv, HX, HY, HXY, HXX) { \
    float xl = __shfl_up_sync(0xffffffffu, xv.y, 1); \
    float xr = __shfl_down_sync(0xffffffffu, xv.x, 1); \
    float yl = __shfl_up_sync(0xffffffffu, yv.y, 1); \
    float yr = __shfl_down_sync(0xffffffffu, yv.x, 1); \
    float mx = xv.x + xv.y; \
    float my = yv.x + yv.y; \
    HX.x = xl + mx;  HX.y = mx + xr; \
    HY.x = yl + my;  HY.y = my + yr; \
    float mxy = fmaf(xv.x, yv.x, xv.y * yv.y); \
    float mxx = fmaf(xv.x, xv.x, xv.y * xv.y); \
    HXY.x = fmaf(xl, yl, mxy);  HXY.y = fmaf(xr, yr, mxy); \
    HXX.x = fmaf(xl, xl, mxx);  HXX.y = fmaf(xr, xr, mxx); }

    // A,b9 per element + horizontal 3-sum with col replication: 4 shuffles.
#define ABROW2(Sx, Sy, Sxy, Sxx, HA, HB) { \
    float2 A, B; \
    { float t = Sx.x * Sy.x; \
      float num = fmaf(Sxy.x, 9.0f, -t); \
      float u   = fmaf(-Sx.x, Sx.x, EPS81); \
      float den = fmaf(Sxx.x, 9.0f, u); \
      A.x = __fdividef(num, den); \
      B.x = fmaf(-A.x, Sx.x, Sy.x); } \
    { float t = Sx.y * Sy.y; \
      float num = fmaf(Sxy.y, 9.0f, -t); \
      float u   = fmaf(-Sx.y, Sx.y, EPS81); \
      float den = fmaf(Sxx.y, 9.0f, u); \
      A.y = __fdividef(num, den); \
      B.y = fmaf(-A.y, Sx.y, Sy.y); } \
    float Al = __shfl_up_sync(0xffffffffu, A.y, 1); \
    float Ar = __shfl_down_sync(0xffffffffu, A.x, 1); \
    float Bl = __shfl_up_sync(0xffffffffu, B.y, 1); \
    float Br = __shfl_down_sync(0xffffffffu, B.x, 1); \
    if (pl) { Al = A.x;  Bl = B.x; } \
    if (pr) { Ar = A.y;  Br = B.y; } \
    float ma = A.x + A.y, mb = B.x + B.y; \
    HA.x = Al + ma;  HA.y = ma + Ar; \
    HB.x = Bl + mb;  HB.y = mb + Br; }

#define ADD2(r, a, b) { r.x = a.x + b.x;  r.y = a.y + b.y; }

    // Sliding-sum state (invariant at top of step for output row rr):
    //   hp* = h at input row rr+1,  P* = h[rr] + h[rr+1]
    //   hAp = hA at A-row rr,       PA = hA[rr-1] + hA[rr]   (B likewise)
    //   xc0 = x[rr], xc1 = x[rr+1]; (nxv,nyv) = input row min(rr+2,H-1)
    float2 hpx, hpy, hpxy, hpxx, Px, Py, Pxy, Pxx;
    float2 hAp, hBp, PA, PB;
    float2 xc0, xc1, nxv, nyv;

    // ---------------- prologue ----------------
    {
        float2 t0x, t0y, t0xy, t0xx, t1x, t1y, t1xy, t1xx;
        float2 h0x, h0y, h0xy, h0xx, h1x, h1y, h1xy, h1xx;
        float2 xv, yv;
        LD2(xv, px, max(r0 - 2, 0))  LD2(yv, py, max(r0 - 2, 0))
        HQ2(xv, yv, t0x, t0y, t0xy, t0xx)
        LD2(xv, px, max(r0 - 1, 0))  LD2(yv, py, max(r0 - 1, 0))
        HQ2(xv, yv, t1x, t1y, t1xy, t1xx)
        LD2(xv, px, r0)              LD2(yv, py, r0)
        HQ2(xv, yv, h0x, h0y, h0xy, h0xx)  xc0 = xv;
        LD2(xv, px, r0 + 1)          LD2(yv, py, r0 + 1)
        HQ2(xv, yv, h1x, h1y, h1xy, h1xx)  xc1 = xv;

        float2 Sx, Sy, Sxy, Sxx, hAm, hBm, hA0, hB0;
        Sx.x = t0x.x + t1x.x + h0x.x;    Sx.y = t0x.y + t1x.y + h0x.y;
        Sy.x = t0y.x + t1y.x + h0y.x;    Sy.y = t0y.y + t1y.y + h0y.y;
        Sxy.x = t0xy.x + t1xy.x + h0xy.x; Sxy.y = t0xy.y + t1xy.y + h0xy.y;
        Sxx.x = t0xx.x + t1xx.x + h0xx.x; Sxx.y = t0xx.y + t1xx.y + h0xx.y;
        ABROW2(Sx, Sy, Sxy, Sxx, hAm, hBm)                 // A row r0-1
        Sx.x = t1x.x + h0x.x + h1x.x;    Sx.y = t1x.y + h0x.y + h1x.y;
        Sy.x = t1y.x + h0y.x + h1y.x;    Sy.y = t1y.y + h0y.y + h1y.y;
        Sxy.x = t1xy.x + h0xy.x + h1xy.x; Sxy.y = t1xy.y + h0xy.y + h1xy.y;
        Sxx.x = t1xx.x + h0xx.x + h1xx.x; Sxx.y = t1xx.y + h0xx.y + h1xx.y;
        ABROW2(Sx, Sy, Sxy, Sxx, hA0, hB0)                 // A row r0
        if (r0 == 0) { hAm = hA0;  hBm = hB0; }            // top: A(-1) := A(0)

        hpx = h1x;  hpy = h1y;  hpxy = h1xy;  hpxx = h1xx;
        ADD2(Px, h0x, h1x)    ADD2(Py, h0y, h1y)
        ADD2(Pxy, h0xy, h1xy) ADD2(Pxx, h0xx, h1xx)
        hAp = hA0;  hBp = hB0;
        ADD2(PA, hAm, hA0)    ADD2(PB, hBm, hB0)
    }

    const float* pxr = px + (size_t)(r0 + 3) * W;  // r0+3 <= 899, always valid
    const float* pyr = py + (size_t)(r0 + 3) * W;
    LD2(nxv, px, r0 + 2)
    LD2(nyv, py, r0 + 2)

    // Core of one step (input row rr+2 in xv/yv).
#define SCORE(xv, yv) \
    float2 nx_, ny_, nxy_, nxx_; \
    HQ2(xv, yv, nx_, ny_, nxy_, nxx_) \
    float2 Sx, Sy, Sxy, Sxx; \
    ADD2(Sx, Px, nx_)   ADD2(Sy, Py, ny_) \
    ADD2(Sxy, Pxy, nxy_) ADD2(Sxx, Pxx, nxx_) \
    ADD2(Px, hpx, nx_)  ADD2(Py, hpy, ny_) \
    ADD2(Pxy, hpxy, nxy_) ADD2(Pxx, hpxx, nxx_) \
    hpx = nx_;  hpy = ny_;  hpxy = nxy_;  hpxx = nxx_; \
    float2 hAn, hBn; \
    ABROW2(Sx, Sy, Sxy, Sxx, hAn, hBn)

#define STAIL(xv) \
    float2 SA, SB; \
    ADD2(SA, PA, hAn)  ADD2(SB, PB, hBn) \
    ADD2(PA, hAp, hAn) ADD2(PB, hBp, hBn) \
    hAp = hAn;  hBp = hBn; \
    float2 res; \
    res.x = fminf(fmaxf(truncf(fmaf(SA.x, xc0.x, SB.x * C9) * C9), 0.0f), 255.0f); \
    res.y = fminf(fmaxf(truncf(fmaf(SA.y, xc0.y, SB.y * C9) * C9), 0.0f), 255.0f); \
    if (do_store) *reinterpret_cast<float2*>(po) = res; \
    po += W; \
    xc0 = xc1;  xc1 = xv;

    // Guard-free steps i = 0..123 (needs rr+3 <= H-1; last chunk ok to i=124).
#pragma unroll 4
    for (int i = 0; i < CHUNK_H - 4; ++i) {
        float2 xv = nxv, yv = nyv;
        LDP(nxv, pxr)  LDP(nyv, pyr)
        pxr += W;  pyr += W;
        SCORE(xv, yv)
        STAIL(xv)
    }

    // Guarded steps i = 124..127 (bottom replication; no-ops for inner chunks).
#define STEP_G(i) { \
        const int rr = r0 + (i); \
        float2 xv = nxv, yv = nyv; \
        LDP(nxv, pxr)  LDP(nyv, pyr) \
        if (rr + 4 < H) { pxr += W;  pyr += W; } \
        SCORE(xv, yv) \
        if (rr + 1 >= H) { hAn = hAp;  hBn = hBp; }   /* A(H) := A(H-1) */ \
        STAIL(xv) }

    STEP_G(CHUNK_H - 4)
    STEP_G(CHUNK_H - 3)
    STEP_G(CHUNK_H - 2)
    STEP_G(CHUNK_H - 1)
#undef STEP_G
#undef STAIL
#undef SCORE
#undef ADD2
#undef ABROW2
#undef HQ2
#undef LDP
#undef LD2
}

extern "C" void kernel_launch(void* const* d_in, const int* in_sizes, int n_in,
                              void* d_out, int out_size) {
    const float* x = (const float*)d_in[0];
    const float* y = (const float*)d_in[1];
    float* out     = (float*)d_out;

    gf_kernel<<<NBLOCKS, 32 * WPB>>>(x, y, out);
}

// round 12
// speedup vs baseline: 1.0332x; 1.0078x over previous
#include <cuda_runtime.h>

// Guided filter, fully fused, SMEM-free warp-sliding, 2 columns per lane.
// R11 (82.7us) with 10 chunks per column instead of 8: 4320 warps (29.2/SM)
// vs 3456 (23.4/SM), still a single wave (1080 blocks < 1184 = 148 SMs x 8
// blocks @ 64 regs). Per warp-step: 8 SHFL + 2 LDG.64 + 1 STG.64 for 60
// outputs. Sliding-sum state, pointer-bump prefetch, unroll-4 loop.

#define W 1024
#define H 1024
#define EPS81 8.1e-5f           // 81 * 1e-6
#define C9 (1.0f / 9.0f)

#define OUTC 60
#define BANDS 18                // ceil(1024/60)
#define CH_BASE 103             // chunk height (last chunk: 1024-9*103 = 97)
#define CHUNKS 10
#define WPB 4                   // 128 threads
#define UNITS (24 * BANDS * CHUNKS)        // 4320 warps
#define NBLOCKS (UNITS / WPB)              // 1080 blocks (single wave)

__global__ __launch_bounds__(128, 8) void gf_kernel(const float* __restrict__ x,
                                                    const float* __restrict__ y,
                                                    float* __restrict__ out)
{
    const int wid  = threadIdx.x >> 5;
    const int lane = threadIdx.x & 31;
    const int g    = blockIdx.x * WPB + wid;

    const int plane = g / (BANDS * CHUNKS);
    const int rem   = g - plane * (BANDS * CHUNKS);
    const int band  = rem / CHUNKS;
    const int chunk = rem - band * CHUNKS;

    const int cfirst = band * OUTC - 2 + lane * 2;   // this lane's 2 columns
    const int cl     = min(max(cfirst, 0), W - 2);   // clamped aligned load col
    const int r0     = chunk * CH_BASE;
    const int nrows  = min(CH_BASE, H - r0);         // 103, or 97 for last chunk

    const bool dupL = (cfirst < 0);       // lane left of image: both elems = col 0
    const bool dupR = (cfirst >= W);      // lane right of image: both elems = col W-1
    const bool pl   = (cfirst == 0);      // elem .x is image col 0
    const bool pr   = (cfirst == W - 2);  // elem .y is image col 1023
    const bool do_store = (lane >= 1) && (lane <= 30) && (cfirst < W);

    const size_t pb = (size_t)plane * (size_t)(W * H);
    const float* __restrict__ px = x + pb + cl;
    const float* __restrict__ py = y + pb + cl;
    float* po = out + pb + (size_t)r0 * W + cfirst;

    // load + column-replication fixup
#define LD2(v, P, row) { \
    v = *reinterpret_cast<const float2*>((P) + (size_t)(row) * W); \
    if (dupL) v.y = v.x; \
    if (dupR) v.x = v.y; }
#define LDP(v, PTR) { \
    v = *reinterpret_cast<const float2*>(PTR); \
    if (dupL) v.y = v.x; \
    if (dupR) v.x = v.y; }

    // Horizontal 3-sums for a float2 pair: 4 shuffles total.
#define HQ2(xv, yv, HX, HY, HXY, HXX) { \
    float xl = __shfl_up_sync(0xffffffffu, xv.y, 1); \
    float xr = __shfl_down_sync(0xffffffffu, xv.x, 1); \
    float yl = __shfl_up_sync(0xffffffffu, yv.y, 1); \
    float yr = __shfl_down_sync(0xffffffffu, yv.x, 1); \
    float mx = xv.x + xv.y; \
    float my = yv.x + yv.y; \
    HX.x = xl + mx;  HX.y = mx + xr; \
    HY.x = yl + my;  HY.y = my + yr; \
    float mxy = fmaf(xv.x, yv.x, xv.y * yv.y); \
    float mxx = fmaf(xv.x, xv.x, xv.y * xv.y); \
    HXY.x = fmaf(xl, yl, mxy);  HXY.y = fmaf(xr, yr, mxy); \
    HXX.x = fmaf(xl, xl, mxx);  HXX.y = fmaf(xr, xr, mxx); }

    // A,b9 per element + horizontal 3-sum with col replication: 4 shuffles.
#define ABROW2(Sx, Sy, Sxy, Sxx, HA, HB) { \
    float2 A, B; \
    { float t = Sx.x * Sy.x; \
      float num = fmaf(Sxy.x, 9.0f, -t); \
      float u   = fmaf(-Sx.x, Sx.x, EPS81); \
      float den = fmaf(Sxx.x, 9.0f, u); \
      A.x = __fdividef(num, den); \
      B.x = fmaf(-A.x, Sx.x, Sy.x); } \
    { float t = Sx.y * Sy.y; \
      float num = fmaf(Sxy.y, 9.0f, -t); \
      float u   = fmaf(-Sx.y, Sx.y, EPS81); \
      float den = fmaf(Sxx.y, 9.0f, u); \
      A.y = __fdividef(num, den); \
      B.y = fmaf(-A.y, Sx.y, Sy.y); } \
    float Al = __shfl_up_sync(0xffffffffu, A.y, 1); \
    float Ar = __shfl_down_sync(0xffffffffu, A.x, 1); \
    float Bl = __shfl_up_sync(0xffffffffu, B.y, 1); \
    float Br = __shfl_down_sync(0xffffffffu, B.x, 1); \
    if (pl) { Al = A.x;  Bl = B.x; } \
    if (pr) { Ar = A.y;  Br = B.y; } \
    float ma = A.x + A.y, mb = B.x + B.y; \
    HA.x = Al + ma;  HA.y = ma + Ar; \
    HB.x = Bl + mb;  HB.y = mb + Br; }

#define ADD2(r, a, b) { r.x = a.x + b.x;  r.y = a.y + b.y; }

    // Sliding-sum state (invariant at top of step for output row rr):
    //   hp* = h at input row rr+1,  P* = h[rr] + h[rr+1]
    //   hAp = hA at A-row rr,       PA = hA[rr-1] + hA[rr]   (B likewise)
    //   xc0 = x[rr], xc1 = x[rr+1]; (nxv,nyv) = input row min(rr+2,H-1)
    float2 hpx, hpy, hpxy, hpxx, Px, Py, Pxy, Pxx;
    float2 hAp, hBp, PA, PB;
    float2 xc0, xc1, nxv, nyv;

    // ---------------- prologue ----------------
    {
        float2 t0x, t0y, t0xy, t0xx, t1x, t1y, t1xy, t1xx;
        float2 h0x, h0y, h0xy, h0xx, h1x, h1y, h1xy, h1xx;
        float2 xv, yv;
        LD2(xv, px, max(r0 - 2, 0))  LD2(yv, py, max(r0 - 2, 0))
        HQ2(xv, yv, t0x, t0y, t0xy, t0xx)
        LD2(xv, px, max(r0 - 1, 0))  LD2(yv, py, max(r0 - 1, 0))
        HQ2(xv, yv, t1x, t1y, t1xy, t1xx)
        LD2(xv, px, r0)              LD2(yv, py, r0)
        HQ2(xv, yv, h0x, h0y, h0xy, h0xx)  xc0 = xv;
        LD2(xv, px, r0 + 1)          LD2(yv, py, r0 + 1)
        HQ2(xv, yv, h1x, h1y, h1xy, h1xx)  xc1 = xv;

        float2 Sx, Sy, Sxy, Sxx, hAm, hBm, hA0, hB0;
        Sx.x = t0x.x + t1x.x + h0x.x;    Sx.y = t0x.y + t1x.y + h0x.y;
        Sy.x = t0y.x + t1y.x + h0y.x;    Sy.y = t0y.y + t1y.y + h0y.y;
        Sxy.x = t0xy.x + t1xy.x + h0xy.x; Sxy.y = t0xy.y + t1xy.y + h0xy.y;
        Sxx.x = t0xx.x + t1xx.x + h0xx.x; Sxx.y = t0xx.y + t1xx.y + h0xx.y;
        ABROW2(Sx, Sy, Sxy, Sxx, hAm, hBm)                 // A row r0-1
        Sx.x = t1x.x + h0x.x + h1x.x;    Sx.y = t1x.y + h0x.y + h1x.y;
        Sy.x = t1y.x + h0y.x + h1y.x;    Sy.y = t1y.y + h0y.y + h1y.y;
        Sxy.x = t1xy.x + h0xy.x + h1xy.x; Sxy.y = t1xy.y + h0xy.y + h1xy.y;
        Sxx.x = t1xx.x + h0xx.x + h1xx.x; Sxx.y = t1xx.y + h0xx.y + h1xx.y;
        ABROW2(Sx, Sy, Sxy, Sxx, hA0, hB0)                 // A row r0
        if (r0 == 0) { hAm = hA0;  hBm = hB0; }            // top: A(-1) := A(0)

        hpx = h1x;  hpy = h1y;  hpxy = h1xy;  hpxx = h1xx;
        ADD2(Px, h0x, h1x)    ADD2(Py, h0y, h1y)
        ADD2(Pxy, h0xy, h1xy) ADD2(Pxx, h0xx, h1xx)
        hAp = hA0;  hBp = hB0;
        ADD2(PA, hAm, hA0)    ADD2(PB, hBm, hB0)
    }

    const float* pxr = px + (size_t)(r0 + 3) * W;  // r0+3 <= 930, always valid
    const float* pyr = py + (size_t)(r0 + 3) * W;
    LD2(nxv, px, r0 + 2)
    LD2(nyv, py, r0 + 2)

    // Core of one step (input row rr+2 in xv/yv).
#define SCORE(xv, yv) \
    float2 nx_, ny_, nxy_, nxx_; \
    HQ2(xv, yv, nx_, ny_, nxy_, nxx_) \
    float2 Sx, Sy, Sxy, Sxx; \
    ADD2(Sx, Px, nx_)   ADD2(Sy, Py, ny_) \
    ADD2(Sxy, Pxy, nxy_) ADD2(Sxx, Pxx, nxx_) \
    ADD2(Px, hpx, nx_)  ADD2(Py, hpy, ny_) \
    ADD2(Pxy, hpxy, nxy_) ADD2(Pxx, hpxx, nxx_) \
    hpx = nx_;  hpy = ny_;  hpxy = nxy_;  hpxx = nxx_; \
    float2 hAn, hBn; \
    ABROW2(Sx, Sy, Sxy, Sxx, hAn, hBn)

#define STAIL(xv) \
    float2 SA, SB; \
    ADD2(SA, PA, hAn)  ADD2(SB, PB, hBn) \
    ADD2(PA, hAp, hAn) ADD2(PB, hBp, hBn) \
    hAp = hAn;  hBp = hBn; \
    float2 res; \
    res.x = fminf(fmaxf(truncf(fmaf(SA.x, xc0.x, SB.x * C9) * C9), 0.0f), 255.0f); \
    res.y = fminf(fmaxf(truncf(fmaf(SA.y, xc0.y, SB.y * C9) * C9), 0.0f), 255.0f); \
    if (do_store) *reinterpret_cast<float2*>(po) = res; \
    po += W; \
    xc0 = xc1;  xc1 = xv;

    // Guard-free steps i = 0..nrows-5 (requires rr+3 <= H-1; max rr here is
    // r0+nrows-5, so rr+3 = r0+nrows-2 <= 1022 for every chunk).
#pragma unroll 4
    for (int i = 0; i < nrows - 4; ++i) {
        float2 xv = nxv, yv = nyv;
        LDP(nxv, pxr)  LDP(nyv, pyr)
        pxr += W;  pyr += W;
        SCORE(xv, yv)
        STAIL(xv)
    }

    // Guarded steps: last 4 rows of the chunk (bottom replication for the
    // final chunk; plain steps otherwise).
    const int rbase = r0 + nrows - 4;
#define STEP_G(k) { \
        const int rr = rbase + (k); \
        float2 xv = nxv, yv = nyv; \
        LDP(nxv, pxr)  LDP(nyv, pyr) \
        if (rr + 4 < H) { pxr += W;  pyr += W; } \
        SCORE(xv, yv) \
        if (rr + 1 >= H) { hAn = hAp;  hBn = hBp; }   /* A(H) := A(H-1) */ \
        STAIL(xv) }

    STEP_G(0)
    STEP_G(1)
    STEP_G(2)
    STEP_G(3)
#undef STEP_G
#undef STAIL
#undef SCORE
#undef ADD2
#undef ABROW2
#undef HQ2
#undef LDP
#undef LD2
}

extern "C" void kernel_launch(void* const* d_in, const int* in_sizes, int n_in,
                              void* d_out, int out_size) {
    const float* x = (const float*)d_in[0];
    const float* y = (const float*)d_in[1];
    float* out     = (float*)d_out;

    gf_kernel<<<NBLOCKS, 32 * WPB>>>(x, y, out);
}

// round 13
// speedup vs baseline: 1.1810x; 1.1431x over previous
#include <cuda_runtime.h>

// Guided filter, fully fused, SMEM-free warp-sliding, 2 columns per lane.
// R12 with UNIFORM chunk height: all 10 chunks process exactly 103 rows; the
// last chunk is anchored at r0 = 921 and overlaps chunk 8 on rows 921..926
// (identical values written twice -- benign). Constant trip count (99 = 33*3)
// restores clean unrolled codegen (R12's dynamic bound cost ~7% extra ALU).

#define W 1024
#define H 1024
#define EPS81 8.1e-5f           // 81 * 1e-6
#define C9 (1.0f / 9.0f)

#define OUTC 60
#define BANDS 18                // ceil(1024/60)
#define CH 103                  // uniform chunk height
#define CHUNKS 10
#define WPB 4                   // 128 threads
#define UNITS (24 * BANDS * CHUNKS)        // 4320 warps
#define NBLOCKS (UNITS / WPB)              // 1080 blocks (single wave)

__global__ __launch_bounds__(128, 8) void gf_kernel(const float* __restrict__ x,
                                                    const float* __restrict__ y,
                                                    float* __restrict__ out)
{
    const int wid  = threadIdx.x >> 5;
    const int lane = threadIdx.x & 31;
    const int g    = blockIdx.x * WPB + wid;

    const int plane = g / (BANDS * CHUNKS);
    const int rem   = g - plane * (BANDS * CHUNKS);
    const int band  = rem / CHUNKS;
    const int chunk = rem - band * CHUNKS;

    const int cfirst = band * OUTC - 2 + lane * 2;   // this lane's 2 columns
    const int cl     = min(max(cfirst, 0), W - 2);   // clamped aligned load col
    const int r0     = min(chunk * CH, H - CH);      // last chunk anchored at 921

    const bool dupL = (cfirst < 0);       // lane left of image: both elems = col 0
    const bool dupR = (cfirst >= W);      // lane right of image: both elems = col W-1
    const bool pl   = (cfirst == 0);      // elem .x is image col 0
    const bool pr   = (cfirst == W - 2);  // elem .y is image col 1023
    const bool do_store = (lane >= 1) && (lane <= 30) && (cfirst < W);

    const size_t pb = (size_t)plane * (size_t)(W * H);
    const float* __restrict__ px = x + pb + cl;
    const float* __restrict__ py = y + pb + cl;
    float* po = out + pb + (size_t)r0 * W + cfirst;

    // load + column-replication fixup
#define LD2(v, P, row) { \
    v = *reinterpret_cast<const float2*>((P) + (size_t)(row) * W); \
    if (dupL) v.y = v.x; \
    if (dupR) v.x = v.y; }
#define LDP(v, PTR) { \
    v = *reinterpret_cast<const float2*>(PTR); \
    if (dupL) v.y = v.x; \
    if (dupR) v.x = v.y; }

    // Horizontal 3-sums for a float2 pair: 4 shuffles total.
#define HQ2(xv, yv, HX, HY, HXY, HXX) { \
    float xl = __shfl_up_sync(0xffffffffu, xv.y, 1); \
    float xr = __shfl_down_sync(0xffffffffu, xv.x, 1); \
    float yl = __shfl_up_sync(0xffffffffu, yv.y, 1); \
    float yr = __shfl_down_sync(0xffffffffu, yv.x, 1); \
    float mx = xv.x + xv.y; \
    float my = yv.x + yv.y; \
    HX.x = xl + mx;  HX.y = mx + xr; \
    HY.x = yl + my;  HY.y = my + yr; \
    float mxy = fmaf(xv.x, yv.x, xv.y * yv.y); \
    float mxx = fmaf(xv.x, xv.x, xv.y * xv.y); \
    HXY.x = fmaf(xl, yl, mxy);  HXY.y = fmaf(xr, yr, mxy); \
    HXX.x = fmaf(xl, xl, mxx);  HXX.y = fmaf(xr, xr, mxx); }

    // A,b9 per element + horizontal 3-sum with col replication: 4 shuffles.
#define ABROW2(Sx, Sy, Sxy, Sxx, HA, HB) { \
    float2 A, B; \
    { float t = Sx.x * Sy.x; \
      float num = fmaf(Sxy.x, 9.0f, -t); \
      float u   = fmaf(-Sx.x, Sx.x, EPS81); \
      float den = fmaf(Sxx.x, 9.0f, u); \
      A.x = __fdividef(num, den); \
      B.x = fmaf(-A.x, Sx.x, Sy.x); } \
    { float t = Sx.y * Sy.y; \
      float num = fmaf(Sxy.y, 9.0f, -t); \
      float u   = fmaf(-Sx.y, Sx.y, EPS81); \
      float den = fmaf(Sxx.y, 9.0f, u); \
      A.y = __fdividef(num, den); \
      B.y = fmaf(-A.y, Sx.y, Sy.y); } \
    float Al = __shfl_up_sync(0xffffffffu, A.y, 1); \
    float Ar = __shfl_down_sync(0xffffffffu, A.x, 1); \
    float Bl = __shfl_up_sync(0xffffffffu, B.y, 1); \
    float Br = __shfl_down_sync(0xffffffffu, B.x, 1); \
    if (pl) { Al = A.x;  Bl = B.x; } \
    if (pr) { Ar = A.y;  Br = B.y; } \
    float ma = A.x + A.y, mb = B.x + B.y; \
    HA.x = Al + ma;  HA.y = ma + Ar; \
    HB.x = Bl + mb;  HB.y = mb + Br; }

#define ADD2(r, a, b) { r.x = a.x + b.x;  r.y = a.y + b.y; }

    // Sliding-sum state (invariant at top of step for output row rr):
    //   hp* = h at input row rr+1,  P* = h[rr] + h[rr+1]
    //   hAp = hA at A-row rr,       PA = hA[rr-1] + hA[rr]   (B likewise)
    //   xc0 = x[rr], xc1 = x[rr+1]; (nxv,nyv) = input row min(rr+2,H-1)
    float2 hpx, hpy, hpxy, hpxx, Px, Py, Pxy, Pxx;
    float2 hAp, hBp, PA, PB;
    float2 xc0, xc1, nxv, nyv;

    // ---------------- prologue ----------------
    {
        float2 t0x, t0y, t0xy, t0xx, t1x, t1y, t1xy, t1xx;
        float2 h0x, h0y, h0xy, h0xx, h1x, h1y, h1xy, h1xx;
        float2 xv, yv;
        LD2(xv, px, max(r0 - 2, 0))  LD2(yv, py, max(r0 - 2, 0))
        HQ2(xv, yv, t0x, t0y, t0xy, t0xx)
        LD2(xv, px, max(r0 - 1, 0))  LD2(yv, py, max(r0 - 1, 0))
        HQ2(xv, yv, t1x, t1y, t1xy, t1xx)
        LD2(xv, px, r0)              LD2(yv, py, r0)
        HQ2(xv, yv, h0x, h0y, h0xy, h0xx)  xc0 = xv;
        LD2(xv, px, r0 + 1)          LD2(yv, py, r0 + 1)
        HQ2(xv, yv, h1x, h1y, h1xy, h1xx)  xc1 = xv;

        float2 Sx, Sy, Sxy, Sxx, hAm, hBm, hA0, hB0;
        Sx.x = t0x.x + t1x.x + h0x.x;    Sx.y = t0x.y + t1x.y + h0x.y;
        Sy.x = t0y.x + t1y.x + h0y.x;    Sy.y = t0y.y + t1y.y + h0y.y;
        Sxy.x = t0xy.x + t1xy.x + h0xy.x; Sxy.y = t0xy.y + t1xy.y + h0xy.y;
        Sxx.x = t0xx.x + t1xx.x + h0xx.x; Sxx.y = t0xx.y + t1xx.y + h0xx.y;
        ABROW2(Sx, Sy, Sxy, Sxx, hAm, hBm)                 // A row r0-1
        Sx.x = t1x.x + h0x.x + h1x.x;    Sx.y = t1x.y + h0x.y + h1x.y;
        Sy.x = t1y.x + h0y.x + h1y.x;    Sy.y = t1y.y + h0y.y + h1y.y;
        Sxy.x = t1xy.x + h0xy.x + h1xy.x; Sxy.y = t1xy.y + h0xy.y + h1xy.y;
        Sxx.x = t1xx.x + h0xx.x + h1xx.x; Sxx.y = t1xx.y + h0xx.y + h1xx.y;
        ABROW2(Sx, Sy, Sxy, Sxx, hA0, hB0)                 // A row r0
        if (r0 == 0) { hAm = hA0;  hBm = hB0; }            // top: A(-1) := A(0)

        hpx = h1x;  hpy = h1y;  hpxy = h1xy;  hpxx = h1xx;
        ADD2(Px, h0x, h1x)    ADD2(Py, h0y, h1y)
        ADD2(Pxy, h0xy, h1xy) ADD2(Pxx, h0xx, h1xx)
        hAp = hA0;  hBp = hB0;
        ADD2(PA, hAm, hA0)    ADD2(PB, hBm, hB0)
    }

    const float* pxr = px + (size_t)(r0 + 3) * W;  // r0+3 <= 924, always valid
    const float* pyr = py + (size_t)(r0 + 3) * W;
    LD2(nxv, px, r0 + 2)
    LD2(nyv, py, r0 + 2)

    // Core of one step (input row rr+2 in xv/yv).
#define SCORE(xv, yv) \
    float2 nx_, ny_, nxy_, nxx_; \
    HQ2(xv, yv, nx_, ny_, nxy_, nxx_) \
    float2 Sx, Sy, Sxy, Sxx; \
    ADD2(Sx, Px, nx_)   ADD2(Sy, Py, ny_) \
    ADD2(Sxy, Pxy, nxy_) ADD2(Sxx, Pxx, nxx_) \
    ADD2(Px, hpx, nx_)  ADD2(Py, hpy, ny_) \
    ADD2(Pxy, hpxy, nxy_) ADD2(Pxx, hpxx, nxx_) \
    hpx = nx_;  hpy = ny_;  hpxy = nxy_;  hpxx = nxx_; \
    float2 hAn, hBn; \
    ABROW2(Sx, Sy, Sxy, Sxx, hAn, hBn)

#define STAIL(xv) \
    float2 SA, SB; \
    ADD2(SA, PA, hAn)  ADD2(SB, PB, hBn) \
    ADD2(PA, hAp, hAn) ADD2(PB, hBp, hBn) \
    hAp = hAn;  hBp = hBn; \
    float2 res; \
    res.x = fminf(fmaxf(truncf(fmaf(SA.x, xc0.x, SB.x * C9) * C9), 0.0f), 255.0f); \
    res.y = fminf(fmaxf(truncf(fmaf(SA.y, xc0.y, SB.y * C9) * C9), 0.0f), 255.0f); \
    if (do_store) *reinterpret_cast<float2*>(po) = res; \
    po += W; \
    xc0 = xc1;  xc1 = xv;

    // Guard-free steps i = 0..98 (99 = 33*3 iterations, compile-time constant).
    // Safe: max rr = r0+98 -> rr+3 = r0+101 <= 1022 for every chunk (r0 <= 921).
#pragma unroll 3
    for (int i = 0; i < CH - 4; ++i) {
        float2 xv = nxv, yv = nyv;
        LDP(nxv, pxr)  LDP(nyv, pyr)
        pxr += W;  pyr += W;
        SCORE(xv, yv)
        STAIL(xv)
    }

    // Guarded steps: last 4 rows of the chunk (bottom replication only fires
    // for the r0 == 921 chunk; plain steps otherwise).
    const int rbase = r0 + CH - 4;
#define STEP_G(k) { \
        const int rr = rbase + (k); \
        float2 xv = nxv, yv = nyv; \
        LDP(nxv, pxr)  LDP(nyv, pyr) \
        if (rr + 4 < H) { pxr += W;  pyr += W; } \
        SCORE(xv, yv) \
        if (rr + 1 >= H) { hAn = hAp;  hBn = hBp; }   /* A(H) := A(H-1) */ \
        STAIL(xv) }

    STEP_G(0)
    STEP_G(1)
    STEP_G(2)
    STEP_G(3)
#undef STEP_G
#undef STAIL
#undef SCORE
#undef ADD2
#undef ABROW2
#undef HQ2
#undef LDP
#undef LD2
}

extern "C" void kernel_launch(void* const* d_in, const int* in_sizes, int n_in,
                              void* d_out, int out_size) {
    const float* x = (const float*)d_in[0];
    const float* y = (const float*)d_in[1];
    float* out     = (float*)d_out;

    gf_kernel<<<NBLOCKS, 32 * WPB>>>(x, y, out);
}

// round 14
// speedup vs baseline: 1.2344x; 1.0452x over previous
#include <cuda_runtime.h>

// Guided filter, fully fused, SMEM-free warp-sliding, 2 columns per lane.
// R13 (71.8us) with 11 uniform chunks of CH=94 instead of 10x103: supplies
// 4752 warps = 32.1/SM, exactly the 64-reg residency cap (was 29.2/SM).
// Last chunk anchored at r0=930; overlap rows recomputed identically (benign).
// Constant trip count 90 = 30*3 keeps the clean unrolled codegen.

#define W 1024
#define H 1024
#define EPS81 8.1e-5f           // 81 * 1e-6
#define C9 (1.0f / 9.0f)

#define OUTC 60
#define BANDS 18                // ceil(1024/60)
#define CH 94                   // uniform chunk height
#define CHUNKS 11
#define WPB 4                   // 128 threads
#define UNITS (24 * BANDS * CHUNKS)        // 4752 warps
#define NBLOCKS (UNITS / WPB)              // 1188 blocks

__global__ __launch_bounds__(128, 8) void gf_kernel(const float* __restrict__ x,
                                                    const float* __restrict__ y,
                                                    float* __restrict__ out)
{
    const int wid  = threadIdx.x >> 5;
    const int lane = threadIdx.x & 31;
    const int g    = blockIdx.x * WPB + wid;

    const int plane = g / (BANDS * CHUNKS);
    const int rem   = g - plane * (BANDS * CHUNKS);
    const int band  = rem / CHUNKS;
    const int chunk = rem - band * CHUNKS;

    const int cfirst = band * OUTC - 2 + lane * 2;   // this lane's 2 columns
    const int cl     = min(max(cfirst, 0), W - 2);   // clamped aligned load col
    const int r0     = min(chunk * CH, H - CH);      // last chunk anchored at 930

    const bool dupL = (cfirst < 0);       // lane left of image: both elems = col 0
    const bool dupR = (cfirst >= W);      // lane right of image: both elems = col W-1
    const bool pl   = (cfirst == 0);      // elem .x is image col 0
    const bool pr   = (cfirst == W - 2);  // elem .y is image col 1023
    const bool do_store = (lane >= 1) && (lane <= 30) && (cfirst < W);

    const size_t pb = (size_t)plane * (size_t)(W * H);
    const float* __restrict__ px = x + pb + cl;
    const float* __restrict__ py = y + pb + cl;
    float* po = out + pb + (size_t)r0 * W + cfirst;

    // load + column-replication fixup
#define LD2(v, P, row) { \
    v = *reinterpret_cast<const float2*>((P) + (size_t)(row) * W); \
    if (dupL) v.y = v.x; \
    if (dupR) v.x = v.y; }
#define LDP(v, PTR) { \
    v = *reinterpret_cast<const float2*>(PTR); \
    if (dupL) v.y = v.x; \
    if (dupR) v.x = v.y; }

    // Horizontal 3-sums for a float2 pair: 4 shuffles total.
#define HQ2(xv, yv, HX, HY, HXY, HXX) { \
    float xl = __shfl_up_sync(0xffffffffu, xv.y, 1); \
    float xr = __shfl_down_sync(0xffffffffu, xv.x, 1); \
    float yl = __shfl_up_sync(0xffffffffu, yv.y, 1); \
    float yr = __shfl_down_sync(0xffffffffu, yv.x, 1); \
    float mx = xv.x + xv.y; \
    float my = yv.x + yv.y; \
    HX.x = xl + mx;  HX.y = mx + xr; \
    HY.x = yl + my;  HY.y = my + yr; \
    float mxy = fmaf(xv.x, yv.x, xv.y * yv.y); \
    float mxx = fmaf(xv.x, xv.x, xv.y * xv.y); \
    HXY.x = fmaf(xl, yl, mxy);  HXY.y = fmaf(xr, yr, mxy); \
    HXX.x = fmaf(xl, xl, mxx);  HXX.y = fmaf(xr, xr, mxx); }

    // A,b9 per element + horizontal 3-sum with col replication: 4 shuffles.
#define ABROW2(Sx, Sy, Sxy, Sxx, HA, HB) { \
    float2 A, B; \
    { float t = Sx.x * Sy.x; \
      float num = fmaf(Sxy.x, 9.0f, -t); \
      float u   = fmaf(-Sx.x, Sx.x, EPS81); \
      float den = fmaf(Sxx.x, 9.0f, u); \
      A.x = __fdividef(num, den); \
      B.x = fmaf(-A.x, Sx.x, Sy.x); } \
    { float t = Sx.y * Sy.y; \
      float num = fmaf(Sxy.y, 9.0f, -t); \
      float u   = fmaf(-Sx.y, Sx.y, EPS81); \
      float den = fmaf(Sxx.y, 9.0f, u); \
      A.y = __fdividef(num, den); \
      B.y = fmaf(-A.y, Sx.y, Sy.y); } \
    float Al = __shfl_up_sync(0xffffffffu, A.y, 1); \
    float Ar = __shfl_down_sync(0xffffffffu, A.x, 1); \
    float Bl = __shfl_up_sync(0xffffffffu, B.y, 1); \
    float Br = __shfl_down_sync(0xffffffffu, B.x, 1); \
    if (pl) { Al = A.x;  Bl = B.x; } \
    if (pr) { Ar = A.y;  Br = B.y; } \
    float ma = A.x + A.y, mb = B.x + B.y; \
    HA.x = Al + ma;  HA.y = ma + Ar; \
    HB.x = Bl + mb;  HB.y = mb + Br; }

#define ADD2(r, a, b) { r.x = a.x + b.x;  r.y = a.y + b.y; }

    // Sliding-sum state (invariant at top of step for output row rr):
    //   hp* = h at input row rr+1,  P* = h[rr] + h[rr+1]
    //   hAp = hA at A-row rr,       PA = hA[rr-1] + hA[rr]   (B likewise)
    //   xc0 = x[rr], xc1 = x[rr+1]; (nxv,nyv) = input row min(rr+2,H-1)
    float2 hpx, hpy, hpxy, hpxx, Px, Py, Pxy, Pxx;
    float2 hAp, hBp, PA, PB;
    float2 xc0, xc1, nxv, nyv;

    // ---------------- prologue ----------------
    {
        float2 t0x, t0y, t0xy, t0xx, t1x, t1y, t1xy, t1xx;
        float2 h0x, h0y, h0xy, h0xx, h1x, h1y, h1xy, h1xx;
        float2 xv, yv;
        LD2(xv, px, max(r0 - 2, 0))  LD2(yv, py, max(r0 - 2, 0))
        HQ2(xv, yv, t0x, t0y, t0xy, t0xx)
        LD2(xv, px, max(r0 - 1, 0))  LD2(yv, py, max(r0 - 1, 0))
        HQ2(xv, yv, t1x, t1y, t1xy, t1xx)
        LD2(xv, px, r0)              LD2(yv, py, r0)
        HQ2(xv, yv, h0x, h0y, h0xy, h0xx)  xc0 = xv;
        LD2(xv, px, r0 + 1)          LD2(yv, py, r0 + 1)
        HQ2(xv, yv, h1x, h1y, h1xy, h1xx)  xc1 = xv;

        float2 Sx, Sy, Sxy, Sxx, hAm, hBm, hA0, hB0;
        Sx.x = t0x.x + t1x.x + h0x.x;    Sx.y = t0x.y + t1x.y + h0x.y;
        Sy.x = t0y.x + t1y.x + h0y.x;    Sy.y = t0y.y + t1y.y + h0y.y;
        Sxy.x = t0xy.x + t1xy.x + h0xy.x; Sxy.y = t0xy.y + t1xy.y + h0xy.y;
        Sxx.x = t0xx.x + t1xx.x + h0xx.x; Sxx.y = t0xx.y + t1xx.y + h0xx.y;
        ABROW2(Sx, Sy, Sxy, Sxx, hAm, hBm)                 // A row r0-1
        Sx.x = t1x.x + h0x.x + h1x.x;    Sx.y = t1x.y + h0x.y + h1x.y;
        Sy.x = t1y.x + h0y.x + h1y.x;    Sy.y = t1y.y + h0y.y + h1y.y;
        Sxy.x = t1xy.x + h0xy.x + h1xy.x; Sxy.y = t1xy.y + h0xy.y + h1xy.y;
        Sxx.x = t1xx.x + h0xx.x + h1xx.x; Sxx.y = t1xx.y + h0xx.y + h1xx.y;
        ABROW2(Sx, Sy, Sxy, Sxx, hA0, hB0)                 // A row r0
        if (r0 == 0) { hAm = hA0;  hBm = hB0; }            // top: A(-1) := A(0)

        hpx = h1x;  hpy = h1y;  hpxy = h1xy;  hpxx = h1xx;
        ADD2(Px, h0x, h1x)    ADD2(Py, h0y, h1y)
        ADD2(Pxy, h0xy, h1xy) ADD2(Pxx, h0xx, h1xx)
        hAp = hA0;  hBp = hB0;
        ADD2(PA, hAm, hA0)    ADD2(PB, hBm, hB0)
    }

    const float* pxr = px + (size_t)(r0 + 3) * W;  // r0+3 <= 933, always valid
    const float* pyr = py + (size_t)(r0 + 3) * W;
    LD2(nxv, px, r0 + 2)
    LD2(nyv, py, r0 + 2)

    // Core of one step (input row rr+2 in xv/yv).
#define SCORE(xv, yv) \
    float2 nx_, ny_, nxy_, nxx_; \
    HQ2(xv, yv, nx_, ny_, nxy_, nxx_) \
    float2 Sx, Sy, Sxy, Sxx; \
    ADD2(Sx, Px, nx_)   ADD2(Sy, Py, ny_) \
    ADD2(Sxy, Pxy, nxy_) ADD2(Sxx, Pxx, nxx_) \
    ADD2(Px, hpx, nx_)  ADD2(Py, hpy, ny_) \
    ADD2(Pxy, hpxy, nxy_) ADD2(Pxx, hpxx, nxx_) \
    hpx = nx_;  hpy = ny_;  hpxy = nxy_;  hpxx = nxx_; \
    float2 hAn, hBn; \
    ABROW2(Sx, Sy, Sxy, Sxx, hAn, hBn)

#define STAIL(xv) \
    float2 SA, SB; \
    ADD2(SA, PA, hAn)  ADD2(SB, PB, hBn) \
    ADD2(PA, hAp, hAn) ADD2(PB, hBp, hBn) \
    hAp = hAn;  hBp = hBn; \
    float2 res; \
    res.x = fminf(fmaxf(truncf(fmaf(SA.x, xc0.x, SB.x * C9) * C9), 0.0f), 255.0f); \
    res.y = fminf(fmaxf(truncf(fmaf(SA.y, xc0.y, SB.y * C9) * C9), 0.0f), 255.0f); \
    if (do_store) *reinterpret_cast<float2*>(po) = res; \
    po += W; \
    xc0 = xc1;  xc1 = xv;

    // Guard-free steps i = 0..89 (90 = 30*3 iterations, compile-time constant).
    // Safe: max rr = r0+89 -> rr+3 = r0+92 <= 1022 for every chunk (r0 <= 930).
#pragma unroll 3
    for (int i = 0; i < CH - 4; ++i) {
        float2 xv = nxv, yv = nyv;
        LDP(nxv, pxr)  LDP(nyv, pyr)
        pxr += W;  pyr += W;
        SCORE(xv, yv)
        STAIL(xv)
    }

    // Guarded steps: last 4 rows of the chunk (bottom replication only fires
    // for the r0 == 930 chunk; plain steps otherwise).
    const int rbase = r0 + CH - 4;
#define STEP_G(k) { \
        const int rr = rbase + (k); \
        float2 xv = nxv, yv = nyv; \
        LDP(nxv, pxr)  LDP(nyv, pyr) \
        if (rr + 4 < H) { pxr += W;  pyr += W; } \
        SCORE(xv, yv) \
        if (rr + 1 >= H) { hAn = hAp;  hBn = hBp; }   /* A(H) := A(H-1) */ \
        STAIL(xv) }

    STEP_G(0)
    STEP_G(1)
    STEP_G(2)
    STEP_G(3)
#undef STEP_G
#undef STAIL
#undef SCORE
#undef ADD2
#undef ABROW2
#undef HQ2
#undef LDP
#undef LD2
}

extern "C" void kernel_launch(void* const* d_in, const int* in_sizes, int n_in,
                              void* d_out, int out_size) {
    const float* x = (const float*)d_in[0];
    const float* y = (const float*)d_in[1];
    float* out     = (float*)d_out;

    gf_kernel<<<NBLOCKS, 32 * WPB>>>(x, y, out);
}